// round 9
// baseline (speedup 1.0000x reference)
#include <cuda_runtime.h>
#include <cuda_fp16.h>
#include <cstdint>

#define BB 32
#define TT 2048
#define DD 512
#define UU 512
#define GRID_P 148          // persistent CTA count (1/SM floor)
#define NTILES 1024         // (BB*TT)/64

// Scratch (no device allocation allowed)
__device__ float g_projh[BB * UU];       // hidden@W2 + b2 + b1 (b1 folded)
__device__ float g_logits[BB * TT];
__device__ float g_stats[BB * 2];        // {max, 1/sum} per batch
__device__ __half g_w1p[UU * DD];        // W1 fp16, fragment-packed, K64 full-N chunks

// ---------------------------------------------------------------------------
// helpers
// ---------------------------------------------------------------------------
__device__ __forceinline__ uint32_t smem_u32(const void* p) {
    uint32_t a;
    asm("{ .reg .u64 t; cvta.to.shared.u64 t, %1; cvt.u32.u64 %0, t; }" : "=r"(a) : "l"(p));
    return a;
}
__device__ __forceinline__ float tanhap(float x) {
    float y;
    asm("tanh.approx.f32 %0, %1;" : "=f"(y) : "f"(x));
    return y;
}
__device__ __forceinline__ void cp16s(uint32_t s, const void* g) {
    asm volatile("cp.async.cg.shared.global [%0], [%1], 16;" :: "r"(s), "l"(g) : "memory");
}
#define CP_COMMIT() asm volatile("cp.async.commit_group;" ::: "memory")

__device__ __forceinline__ uint32_t packh2(float lo, float hi) {
    uint32_t r;
    asm("cvt.rn.f16x2.f32 %0, %1, %2;" : "=r"(r) : "f"(hi), "f"(lo));
    return r;
}
__device__ __forceinline__ void mma_f16(float* c, const uint32_t* a, uint32_t b0, uint32_t b1) {
    asm volatile(
        "mma.sync.aligned.m16n8k16.row.col.f32.f16.f16.f32 "
        "{%0,%1,%2,%3}, {%4,%5,%6,%7}, {%8,%9}, {%0,%1,%2,%3};"
        : "+f"(c[0]), "+f"(c[1]), "+f"(c[2]), "+f"(c[3])
        : "r"(a[0]), "r"(a[1]), "r"(a[2]), "r"(a[3]), "r"(b0), "r"(b1));
}

// ---------------------------------------------------------------------------
// P0 (merged): blocks 0..1023 pack W1; blocks 1024..1055 compute projh.
// W1 pack: chunk kc6 = d>>6 (8 chunks of K64 x U512, 64KB each, linear):
//   off_in_chunk = ((ks*512 + u)*4 + tg)*4 + hidx
//   ks=(d>>4)&3, r=d&15, tg=(r&7)>>1, hidx=(r>>3)*2+(r&1)
// ---------------------------------------------------------------------------
__global__ void prep_kernel(const float* __restrict__ W1,
                            const float* __restrict__ hidden,
                            const float* __restrict__ W2,
                            const float* __restrict__ b1,
                            const float* __restrict__ b2) {
    int bid = blockIdx.x, tid = threadIdx.x;
    if (bid < 1024) {
        int idx = bid * 256 + tid;      // 0..262143
        int d = idx >> 9, u = idx & 511;
        __half v = __float2half_rn(W1[idx]);
        int kc6 = d >> 6, ks = (d >> 4) & 3, r = d & 15;
        int tg = (r & 7) >> 1, hidx = (r >> 3) * 2 + (r & 1);
        g_w1p[(size_t)kc6 * 32768 + ((ks * 512 + u) * 4 + tg) * 4 + hidx] = v;
    } else {
        __shared__ float hs[DD];
        int b = bid - 1024;
        hs[tid] = hidden[b * DD + tid];
        hs[tid + 256] = hidden[b * DD + tid + 256];
        __syncthreads();
#pragma unroll
        for (int h = 0; h < 2; h++) {
            int u = tid + h * 256;
            float acc = b1[u] + b2[u];
#pragma unroll 16
            for (int d = 0; d < DD; d++) acc = fmaf(hs[d], W2[d * UU + u], acc);
            g_projh[b * UU + u] = acc;
        }
    }
}

// ---------------------------------------------------------------------------
// K1: persistent fused GEMM (M=64 tile, N=512, K=512) + tanh + V-contract.
// 1024 tiles over GRID_P CTAs; 8 K64 chunks per tile; B chunks tile-invariant
// (2-stage ring never drains); A converted in-loop one chunk ahead.
// smem: packA[8][8KB] | B[2][64KB] | projh[512] | V[512] | logit[64]
// ---------------------------------------------------------------------------
#define PACKA_OFF 0                    // 65536
#define B_OFF 65536
#define B_STAGE_B 65536
#define PROJ_OFF 196608
#define V_OFF 198656
#define LOG_OFF 200704
#define SMEM_BYTES 200960

__device__ __forceinline__ void load_b(uint32_t sb, int kc, int stage, int tid) {
    uint32_t bbase = sb + B_OFF + stage * B_STAGE_B;
    const __half* Bg = g_w1p + (size_t)kc * 32768;
#pragma unroll
    for (int j = 0; j < 16; j++) {
        int q = tid + j * 256;          // 4096 16B units
        cp16s(bbase + q * 16, Bg + q * 8);
    }
    CP_COMMIT();
}

__device__ __forceinline__ void convertA(char* smem, const float* __restrict__ features,
                                         int m0, int kc, int slot, int tid) {
    uint4* pk = (uint4*)(smem + PACKA_OFF) + slot * 512;
#pragma unroll
    for (int j = 0; j < 2; j++) {
        int q = tid + j * 256;          // 512 fragment-quads
        int ln = q & 31, rest = q >> 5;
        int mt8 = rest >> 2, ks = rest & 3;
        int gq = ln >> 2, tq = ln & 3;
        int mA = mt8 * 16 + gq;
        const float* fA = features + (size_t)(m0 + mA) * DD + kc * 64 + ks * 16 + 2 * tq;
        const float* fB = fA + 8 * DD;
        float2 xA0 = __ldg((const float2*)fA);
        float2 xB0 = __ldg((const float2*)fB);
        float2 xA1 = __ldg((const float2*)(fA + 8));
        float2 xB1 = __ldg((const float2*)(fB + 8));
        uint4 v;
        v.x = packh2(xA0.x, xA0.y);
        v.y = packh2(xB0.x, xB0.y);
        v.z = packh2(xA1.x, xA1.y);
        v.w = packh2(xB1.x, xB1.y);
        pk[q] = v;
    }
}

__global__ void __launch_bounds__(256, 1)
fused_score_kernel(const float* __restrict__ features,
                   const float* __restrict__ V,
                   const float* __restrict__ bv) {
    extern __shared__ __align__(128) char smem[];
    const uint32_t sb = smem_u32(smem);
    const int tid = threadIdx.x;
    const int warp = tid >> 5, lane = tid & 31;
    const int g = lane >> 2, tg = lane & 3;
    const int wm = warp >> 2, wn = warp & 3;       // 2 (M) x 4 (N)

    float* projh_s = (float*)(smem + PROJ_OFF);
    float* Vs = (float*)(smem + V_OFF);
    float* logit_s = (float*)(smem + LOG_OFF);
    const float bv0 = bv[0];

    const int tile0 = blockIdx.x;
    const int nt_mine = (NTILES - tile0 + GRID_P - 1) / GRID_P;
    const int total_cc = nt_mine * 8;

    // prologue
    int m0 = tile0 * 64;
    load_b(sb, 0, 0, tid);
    convertA(smem, features, m0, 0, 0, tid);
    for (int i = tid; i < 512; i += 256) {
        projh_s[i] = g_projh[(tile0 >> 5) * UU + i];
        Vs[i] = V[i];
    }
    if (tid < 64) logit_s[tid] = 0.f;

    const uint4* pkA = (const uint4*)(smem + PACKA_OFF);
    float c[2][16][4];

    for (int cc = 0; cc < total_cc; cc++) {
        const int kc = cc & 7;
        const int s = cc & 1;
        if (kc == 0) {
#pragma unroll
            for (int i = 0; i < 2; i++)
#pragma unroll
                for (int j = 0; j < 16; j++)
#pragma unroll
                    for (int k = 0; k < 4; k++) c[i][j][k] = 0.f;
        }

        asm volatile("cp.async.wait_group 0;" ::: "memory");
        __syncthreads();
        if (cc + 1 < total_cc) load_b(sb, (cc + 1) & 7, (cc + 1) & 1, tid);

        // MMA: warp tile 32x128, 128 m16n8k16 per warp per chunk
        const char* Bs = smem + B_OFF + s * B_STAGE_B;
#pragma unroll
        for (int ks = 0; ks < 4; ks++) {
            uint32_t a[2][4];
#pragma unroll
            for (int mt = 0; mt < 2; mt++) {
                uint4 v = pkA[kc * 512 + ((wm * 2 + mt) * 4 + ks) * 32 + lane];
                a[mt][0] = v.x; a[mt][1] = v.y; a[mt][2] = v.z; a[mt][3] = v.w;
            }
#pragma unroll
            for (int nt = 0; nt < 16; nt++) {
                int nl = wn * 128 + nt * 8 + g;
                uint2 bp = *(const uint2*)(Bs + ((ks * 512 + nl) * 4 + tg) * 8);
                mma_f16(c[0][nt], a[0], bp.x, bp.y);
                mma_f16(c[1][nt], a[1], bp.x, bp.y);
            }
        }

        // convert A for chunk cc+1 (crosses tile boundary at kc==7)
        if (cc + 1 < total_cc) {
            int nxt = cc + 1;
            int tnext = tile0 + (nxt >> 3) * GRID_P;
            convertA(smem, features, tnext * 64, nxt & 7, nxt & 7, tid);
        }

        if (kc == 7) {
            // epilogue: tanh(+projh) . V  ->  logits for this tile
#pragma unroll
            for (int mt = 0; mt < 2; mt++) {
                float p0 = 0.f, p1 = 0.f;
#pragma unroll
                for (int nt = 0; nt < 16; nt++) {
                    int u0 = wn * 128 + nt * 8 + 2 * tg;
                    float ph0 = projh_s[u0], ph1 = projh_s[u0 + 1];
                    float v0 = Vs[u0], v1 = Vs[u0 + 1];
                    p0 += tanhap(c[mt][nt][0] + ph0) * v0;
                    p0 += tanhap(c[mt][nt][1] + ph1) * v1;
                    p1 += tanhap(c[mt][nt][2] + ph0) * v0;
                    p1 += tanhap(c[mt][nt][3] + ph1) * v1;
                }
                p0 += __shfl_xor_sync(0xffffffffu, p0, 1);
                p0 += __shfl_xor_sync(0xffffffffu, p0, 2);
                p1 += __shfl_xor_sync(0xffffffffu, p1, 1);
                p1 += __shfl_xor_sync(0xffffffffu, p1, 2);
                if (tg == 0) {
                    atomicAdd(&logit_s[wm * 32 + mt * 16 + g], p0);
                    atomicAdd(&logit_s[wm * 32 + mt * 16 + 8 + g], p1);
                }
            }
            __syncthreads();
            if (tid < 64) {
                g_logits[m0 + tid] = logit_s[tid] + bv0;
                logit_s[tid] = 0.f;
            }
            // advance to next tile: reload projh (batch changes every tile)
            if (cc + 1 < total_cc) {
                int tnext = tile0 + ((cc + 1) >> 3) * GRID_P;
                m0 = tnext * 64;
                for (int i = tid; i < 512; i += 256)
                    projh_s[i] = g_projh[(tnext >> 5) * UU + i];
            }
        }
    }
}

// ---------------------------------------------------------------------------
// K2: per-batch softmax stats {max, 1/sum}; zeroes context region of d_out.
// ---------------------------------------------------------------------------
__global__ void stats_kernel(float* __restrict__ out) {
    int b = blockIdx.x;
    int tid = threadIdx.x;  // 256
    const float* lg = g_logits + b * TT;

    float vals[8];
    float m = -3.4e38f;
#pragma unroll
    for (int j = 0; j < 8; j++) {
        vals[j] = lg[tid + j * 256];
        m = fmaxf(m, vals[j]);
    }
#pragma unroll
    for (int off = 16; off; off >>= 1) m = fmaxf(m, __shfl_xor_sync(0xffffffffu, m, off));

    __shared__ float red[8];
    __shared__ float stat;
    int warp = tid >> 5, lane = tid & 31;
    if (lane == 0) red[warp] = m;
    __syncthreads();
    if (tid == 0) {
        float mm = red[0];
        for (int i = 1; i < 8; i++) mm = fmaxf(mm, red[i]);
        stat = mm;
    }
    __syncthreads();
    float smax = stat;

    float s = 0.f;
#pragma unroll
    for (int j = 0; j < 8; j++) s += __expf(vals[j] - smax);
#pragma unroll
    for (int off = 16; off; off >>= 1) s += __shfl_xor_sync(0xffffffffu, s, off);
    if (lane == 0) red[warp] = s;
    __syncthreads();
    if (tid == 0) {
        float ss = 0.f;
        for (int i = 0; i < 8; i++) ss += red[i];
        g_stats[b * 2] = smax;
        g_stats[b * 2 + 1] = 1.0f / ss;
    }

    // zero context region (d_out poisoned)
    out[b * DD + tid] = 0.f;
    out[b * DD + 256 + tid] = 0.f;
}

// ---------------------------------------------------------------------------
// K3: attn = exp(logit-m)/s (written to d_out) and
//     context[b,d] += sum_t attn * features[b,t,d]
// ---------------------------------------------------------------------------
__global__ void context_kernel(const float* __restrict__ features,
                               float* __restrict__ out) {
    int b = blockIdx.y;
    int t0 = blockIdx.x * 32;
    int j = threadIdx.x;  // 128 threads, d = 4j
    __shared__ float ws[32];

    float m = g_stats[b * 2], inv = g_stats[b * 2 + 1];
    if (j < 32) {
        float w = __expf(g_logits[b * TT + t0 + j] - m) * inv;
        ws[j] = w;
        out[BB * DD + b * TT + t0 + j] = w;
    }
    __syncthreads();

    const float* fb = features + ((size_t)(b * TT + t0)) * DD + j * 4;
    float4 acc = make_float4(0.f, 0.f, 0.f, 0.f);
#pragma unroll 4
    for (int t = 0; t < 32; t++) {
        float w = ws[t];
        float4 f = *reinterpret_cast<const float4*>(fb + (size_t)t * DD);
        acc.x = fmaf(w, f.x, acc.x);
        acc.y = fmaf(w, f.y, acc.y);
        acc.z = fmaf(w, f.z, acc.z);
        acc.w = fmaf(w, f.w, acc.w);
    }
    float* cp = out + b * DD + j * 4;
    atomicAdd(cp + 0, acc.x);
    atomicAdd(cp + 1, acc.y);
    atomicAdd(cp + 2, acc.z);
    atomicAdd(cp + 3, acc.w);
}

// ---------------------------------------------------------------------------
extern "C" void kernel_launch(void* const* d_in, const int* in_sizes, int n_in,
                              void* d_out, int out_size) {
    const float* features = (const float*)d_in[0];
    const float* hidden   = (const float*)d_in[1];
    const float* W1       = (const float*)d_in[2];
    const float* b1       = (const float*)d_in[3];
    const float* W2       = (const float*)d_in[4];
    const float* b2       = (const float*)d_in[5];
    const float* V        = (const float*)d_in[6];
    const float* bv       = (const float*)d_in[7];
    float* out = (float*)d_out;

    cudaFuncSetAttribute(fused_score_kernel,
                         cudaFuncAttributeMaxDynamicSharedMemorySize, SMEM_BYTES);

    prep_kernel<<<1056, 256>>>(W1, hidden, W2, b1, b2);
    fused_score_kernel<<<GRID_P, 256, SMEM_BYTES>>>(features, V, bv);
    stats_kernel<<<BB, 256>>>(out);
    context_kernel<<<dim3(TT / 32, BB), 128>>>(features, out);
}

// round 11
// speedup vs baseline: 1.0756x; 1.0756x over previous
#include <cuda_runtime.h>
#include <cuda_fp16.h>
#include <cstdint>

#define BB 32
#define TT 2048
#define DD 512
#define UU 512
#define NT 512                 // tiles of 128 rows

// Scratch (no device allocation allowed)
__device__ float g_projh[BB * UU];       // hidden@W2 + b2 + b1 (b1 folded)
__device__ float g_logits[BB * TT];
__device__ float g_tm[NT];               // per-tile logit max
__device__ float g_ts[NT];               // per-tile sum exp(l - m)
__device__ float g_pctx[NT * DD];        // per-tile partial context
__device__ __half g_w1p[UU * DD];        // W1 fp16, fragment-packed

// ---------------------------------------------------------------------------
// helpers
// ---------------------------------------------------------------------------
__device__ __forceinline__ uint32_t smem_u32(const void* p) {
    uint32_t a;
    asm("{ .reg .u64 t; cvta.to.shared.u64 t, %1; cvt.u32.u64 %0, t; }" : "=r"(a) : "l"(p));
    return a;
}
__device__ __forceinline__ float tanhap(float x) {
    float y;
    asm("tanh.approx.f32 %0, %1;" : "=f"(y) : "f"(x));
    return y;
}
__device__ __forceinline__ void cp16s(uint32_t s, const void* g) {
    asm volatile("cp.async.cg.shared.global [%0], [%1], 16;" :: "r"(s), "l"(g) : "memory");
}
#define CP_COMMIT() asm volatile("cp.async.commit_group;" ::: "memory")

__device__ __forceinline__ uint32_t packh2(float lo, float hi) {
    uint32_t r;
    asm("cvt.rn.f16x2.f32 %0, %1, %2;" : "=r"(r) : "f"(hi), "f"(lo));
    return r;
}
__device__ __forceinline__ void mma_f16(float* c, const uint32_t* a, uint32_t b0, uint32_t b1) {
    asm volatile(
        "mma.sync.aligned.m16n8k16.row.col.f32.f16.f16.f32 "
        "{%0,%1,%2,%3}, {%4,%5,%6,%7}, {%8,%9}, {%0,%1,%2,%3};"
        : "+f"(c[0]), "+f"(c[1]), "+f"(c[2]), "+f"(c[3])
        : "r"(a[0]), "r"(a[1]), "r"(a[2]), "r"(a[3]), "r"(b0), "r"(b1));
}

// ---------------------------------------------------------------------------
// P0 (merged): blocks 0..1023 pack W1 (R7 layout); blocks 1024..1055 projh.
// ---------------------------------------------------------------------------
__global__ void prep_kernel(const float* __restrict__ W1,
                            const float* __restrict__ hidden,
                            const float* __restrict__ W2,
                            const float* __restrict__ b1,
                            const float* __restrict__ b2) {
    int bid = blockIdx.x, tid = threadIdx.x;
    if (bid < 1024) {
        int idx = bid * 256 + tid;      // 0..262143
        int d = idx >> 9, u = idx & 511;
        __half v = __float2half_rn(W1[idx]);
        int kc6 = d >> 6, ks = (d >> 4) & 3, r = d & 15;
        int tg = (r & 7) >> 1, hidx = (r >> 3) * 2 + (r & 1);
        int nsub = u >> 7, un = u & 127;
        g_w1p[(size_t)(nsub * 8 + kc6) * 8192 + ((ks * 128 + un) * 4 + tg) * 4 + hidx] = v;
    } else {
        __shared__ float hs[DD];
        int b = bid - 1024;
        hs[tid] = hidden[b * DD + tid];
        hs[tid + 256] = hidden[b * DD + tid + 256];
        __syncthreads();
#pragma unroll
        for (int h = 0; h < 2; h++) {
            int u = tid + h * 256;
            float acc = b1[u] + b2[u];
#pragma unroll 16
            for (int d = 0; d < DD; d++) acc = fmaf(hs[d], W2[d * UU + u], acc);
            g_projh[b * UU + u] = acc;
        }
    }
}

// ---------------------------------------------------------------------------
// K1: fused GEMM 128x512x512 + tanh + V-contract + tile softmax stats +
//     partial context from the fp16 A tile already resident in smem.
// smem: packA[8][16KB] | B[2][32KB] | projh | V(reused as ws/red) | logit
// ---------------------------------------------------------------------------
#define PACKA_OFF 0                    // 131072 B (8 chunks * 16KB)
#define B_OFF 131072
#define B_STAGE_B 32768
#define PROJ_OFF 196608
#define V_OFF 198656
#define LOG_OFF 200704
#define SMEM_BYTES 201216

__device__ __forceinline__ void load_b(uint32_t sb, int c, int tid) {
    uint32_t bbase = sb + B_OFF + (c & 1) * B_STAGE_B;
    const int nc = c >> 3, kc6 = c & 7;
#pragma unroll
    for (int sub = 0; sub < 2; sub++) {
        const __half* Bg = g_w1p + (size_t)((nc * 2 + sub) * 8 + kc6) * 8192;
#pragma unroll
        for (int j = 0; j < 4; j++) {
            int q = tid + j * 256;
            cp16s(bbase + sub * 16384 + q * 16, Bg + q * 8);
        }
    }
    CP_COMMIT();
}

__device__ __forceinline__ void convertA(char* smem, const float* __restrict__ features,
                                         int m0, int kc, int tid) {
    uint4* pk = (uint4*)(smem + PACKA_OFF) + kc * 1024;
#pragma unroll
    for (int j = 0; j < 4; j++) {
        int q = tid + j * 256;
        int ln = q & 31, rest = q >> 5;
        int mt8 = rest >> 2, ks = rest & 3;
        int gq = ln >> 2, tq = ln & 3;
        int mA = mt8 * 16 + gq;
        const float* fA = features + (size_t)(m0 + mA) * DD + kc * 64 + ks * 16 + 2 * tq;
        const float* fB = fA + 8 * DD;
        float2 xA0 = __ldg((const float2*)fA);
        float2 xB0 = __ldg((const float2*)fB);
        float2 xA1 = __ldg((const float2*)(fA + 8));
        float2 xB1 = __ldg((const float2*)(fB + 8));
        uint4 v;
        v.x = packh2(xA0.x, xA0.y);
        v.y = packh2(xB0.x, xB0.y);
        v.z = packh2(xA1.x, xA1.y);
        v.w = packh2(xB1.x, xB1.y);
        pk[q] = v;
    }
}

__global__ void __launch_bounds__(256, 1)
fused_score_kernel(const float* __restrict__ features,
                   const float* __restrict__ V,
                   const float* __restrict__ bv) {
    extern __shared__ __align__(128) char smem[];
    const uint32_t sb = smem_u32(smem);
    const int tid = threadIdx.x;
    const int warp = tid >> 5, lane = tid & 31;
    const int g = lane >> 2, tg = lane & 3;
    const int wm = warp >> 2, wn = warp & 3;
    const int m0 = blockIdx.x * 128;

    float* projh_s = (float*)(smem + PROJ_OFF);
    float* Vs = (float*)(smem + V_OFF);
    float* logit_s = (float*)(smem + LOG_OFF);
    const float bv0 = bv[0];

    load_b(sb, 0, tid);
    convertA(smem, features, m0, 0, tid);
    for (int i = tid; i < 512; i += 256) {
        projh_s[i] = g_projh[(m0 >> 11) * UU + i];
        Vs[i] = V[i];
    }
    if (tid < 128) logit_s[tid] = 0.f;

    const uint4* pkA = (const uint4*)(smem + PACKA_OFF);
    float c[4][8][4];

    for (int cc = 0; cc < 16; cc++) {
        const int s = cc & 1;
        const int kcA = cc & 7;
        if (kcA == 0) {
#pragma unroll
            for (int i = 0; i < 4; i++)
#pragma unroll
                for (int j = 0; j < 8; j++)
#pragma unroll
                    for (int k = 0; k < 4; k++) c[i][j][k] = 0.f;
        }

        asm volatile("cp.async.wait_group 0;" ::: "memory");
        __syncthreads();
        if (cc + 1 < 16) load_b(sb, cc + 1, tid);

        const char* Bs = smem + B_OFF + s * B_STAGE_B + (wn >> 1) * 16384;
        const int nloc0 = (wn & 1) * 64;
#pragma unroll
        for (int ks = 0; ks < 4; ks++) {
            uint32_t a[4][4];
#pragma unroll
            for (int mt = 0; mt < 4; mt++) {
                uint4 v = pkA[kcA * 1024 + ((wm * 4 + mt) * 4 + ks) * 32 + lane];
                a[mt][0] = v.x; a[mt][1] = v.y; a[mt][2] = v.z; a[mt][3] = v.w;
            }
            uint32_t b[8][2];
#pragma unroll
            for (int nt = 0; nt < 8; nt++) {
                int nl = nloc0 + nt * 8 + g;
                uint2 bp = *(const uint2*)(Bs + ((ks * 128 + nl) * 4 + tg) * 8);
                b[nt][0] = bp.x; b[nt][1] = bp.y;
            }
#pragma unroll
            for (int mt = 0; mt < 4; mt++)
#pragma unroll
                for (int nt = 0; nt < 8; nt++)
                    mma_f16(c[mt][nt], a[mt], b[nt][0], b[nt][1]);
        }

        if (cc + 1 < 8) convertA(smem, features, m0, cc + 1, tid);

        if (kcA == 7) {
            const int nc = cc >> 3;
#pragma unroll
            for (int mt = 0; mt < 4; mt++) {
                float p0 = 0.f, p1 = 0.f;
#pragma unroll
                for (int nt = 0; nt < 8; nt++) {
                    int u0 = nc * 256 + wn * 64 + nt * 8 + 2 * tg;
                    float ph0 = projh_s[u0], ph1 = projh_s[u0 + 1];
                    float v0 = Vs[u0], v1 = Vs[u0 + 1];
                    p0 += tanhap(c[mt][nt][0] + ph0) * v0;
                    p0 += tanhap(c[mt][nt][1] + ph1) * v1;
                    p1 += tanhap(c[mt][nt][2] + ph0) * v0;
                    p1 += tanhap(c[mt][nt][3] + ph1) * v1;
                }
                p0 += __shfl_xor_sync(0xffffffffu, p0, 1);
                p0 += __shfl_xor_sync(0xffffffffu, p0, 2);
                p1 += __shfl_xor_sync(0xffffffffu, p1, 1);
                p1 += __shfl_xor_sync(0xffffffffu, p1, 2);
                if (tg == 0) {
                    atomicAdd(&logit_s[wm * 64 + mt * 16 + g], p0);
                    atomicAdd(&logit_s[wm * 64 + mt * 16 + 8 + g], p1);
                }
            }
        }
    }
    __syncthreads();
    if (tid < 128) g_logits[m0 + tid] = logit_s[tid] + bv0;

    // ---- extended epilogue: tile softmax stats + partial context ----
    float* ws = Vs;                 // 128 weights (Vs dead now)
    float* red2 = Vs + 256;         // 8 floats
    if (tid < 128) {
        float l = logit_s[tid] + bv0;
        float mm = l;
#pragma unroll
        for (int off = 16; off; off >>= 1) mm = fmaxf(mm, __shfl_xor_sync(0xffffffffu, mm, off));
        if (lane == 0) red2[warp] = mm;
    }
    __syncthreads();
    float mtile = fmaxf(fmaxf(red2[0], red2[1]), fmaxf(red2[2], red2[3]));
    if (tid < 128) {
        float w = __expf(logit_s[tid] + bv0 - mtile);
        ws[tid] = w;
#pragma unroll
        for (int off = 16; off; off >>= 1) w += __shfl_xor_sync(0xffffffffu, w, off);
        if (lane == 0) red2[4 + warp] = w;
    }
    __syncthreads();
    if (tid == 0) {
        g_tm[blockIdx.x] = mtile;
        g_ts[blockIdx.x] = red2[4] + red2[5] + red2[6] + red2[7];
    }
    // pctx[d] = sum_t ws[t] * feat16[t][d], read from packA fragments
    {
        int d0 = tid * 2;
        int kc = d0 >> 6, rem = d0 & 63;
        int ks = rem >> 4, r2 = rem & 15;
        int pairB = (r2 >> 3) & 1, tq = (r2 & 7) >> 1;
        const char* base = smem + PACKA_OFF + kc * 16384 + ks * 512 + tq * 16 + pairB * 8;
        float a0 = 0.f, a1 = 0.f;
#pragma unroll
        for (int mt8 = 0; mt8 < 8; mt8++) {
#pragma unroll
            for (int gq = 0; gq < 8; gq++) {
                uint2 hv = *(const uint2*)(base + mt8 * 2048 + gq * 64);
                float2 lo = __half22float2(*(const __half2*)&hv.x);
                float2 hi = __half22float2(*(const __half2*)&hv.y);
                float w0 = ws[mt8 * 16 + gq], w1 = ws[mt8 * 16 + gq + 8];
                a0 = fmaf(w0, lo.x, fmaf(w1, hi.x, a0));
                a1 = fmaf(w0, lo.y, fmaf(w1, hi.y, a1));
            }
        }
        g_pctx[(size_t)blockIdx.x * 512 + d0] = a0;
        g_pctx[(size_t)blockIdx.x * 512 + d0 + 1] = a1;
    }
}

// ---------------------------------------------------------------------------
// K2: combine — exact softmax across the 16 tiles of each batch:
//     M = max m_i, S = sum e^{m_i-M} s_i; context and attn outputs.
// ---------------------------------------------------------------------------
__global__ void combine_kernel(float* __restrict__ out) {
    int b = blockIdx.x, tid = threadIdx.x;  // 512 threads
    __shared__ float fw[16];
    __shared__ float sM, sI;
    if (tid == 0) {
        float M = -3.4e38f;
        for (int i = 0; i < 16; i++) M = fmaxf(M, g_tm[b * 16 + i]);
        float S = 0.f;
        for (int i = 0; i < 16; i++) {
            float f = __expf(g_tm[b * 16 + i] - M);
            fw[i] = f;
            S += f * g_ts[b * 16 + i];
        }
        sM = M; sI = 1.0f / S;
    }
    __syncthreads();
    float M = sM, invS = sI;

    float acc = 0.f;
#pragma unroll
    for (int i = 0; i < 16; i++)
        acc = fmaf(fw[i], g_pctx[(size_t)(b * 16 + i) * 512 + tid], acc);
    out[b * DD + tid] = acc * invS;

#pragma unroll
    for (int k = 0; k < 4; k++) {
        int t = tid + k * 512;
        out[BB * DD + b * TT + t] = __expf(g_logits[b * TT + t] - M) * invS;
    }
}

// ---------------------------------------------------------------------------
extern "C" void kernel_launch(void* const* d_in, const int* in_sizes, int n_in,
                              void* d_out, int out_size) {
    const float* features = (const float*)d_in[0];
    const float* hidden   = (const float*)d_in[1];
    const float* W1       = (const float*)d_in[2];
    const float* b1       = (const float*)d_in[3];
    const float* W2       = (const float*)d_in[4];
    const float* b2       = (const float*)d_in[5];
    const float* V        = (const float*)d_in[6];
    const float* bv       = (const float*)d_in[7];
    float* out = (float*)d_out;

    cudaFuncSetAttribute(fused_score_kernel,
                         cudaFuncAttributeMaxDynamicSharedMemorySize, SMEM_BYTES);

    prep_kernel<<<1056, 256>>>(W1, hidden, W2, b1, b2);
    fused_score_kernel<<<NT, 256, SMEM_BYTES>>>(features, V, bv);
    combine_kernel<<<BB, 512>>>(out);
}

// round 13
// speedup vs baseline: 1.2482x; 1.1605x over previous
#include <cuda_runtime.h>
#include <cuda_fp16.h>
#include <cstdint>

#define BB 32
#define TT 2048
#define DD 512
#define UU 512
#define NT 512                 // tiles of 128 rows

// Scratch (no device allocation allowed)
__device__ float g_projh[BB * UU];       // hidden@W2 + b2 + b1 (b1 folded)
__device__ float g_logits[BB * TT];
__device__ float g_tm[NT];               // per-tile logit max
__device__ float g_ts[NT];               // per-tile sum exp(l - m)
__device__ float g_pctx[NT * DD];        // per-tile partial context
__device__ __half g_w1p[UU * DD];        // W1 fp16, fragment-packed

// ---------------------------------------------------------------------------
// helpers
// ---------------------------------------------------------------------------
__device__ __forceinline__ uint32_t smem_u32(const void* p) {
    uint32_t a;
    asm("{ .reg .u64 t; cvta.to.shared.u64 t, %1; cvt.u32.u64 %0, t; }" : "=r"(a) : "l"(p));
    return a;
}
__device__ __forceinline__ float tanhap(float x) {
    float y;
    asm("tanh.approx.f32 %0, %1;" : "=f"(y) : "f"(x));
    return y;
}
__device__ __forceinline__ void cp16s(uint32_t s, const void* g) {
    asm volatile("cp.async.cg.shared.global [%0], [%1], 16;" :: "r"(s), "l"(g) : "memory");
}
#define CP_COMMIT() asm volatile("cp.async.commit_group;" ::: "memory")

__device__ __forceinline__ uint32_t packh2(float lo, float hi) {
    uint32_t r;
    asm("cvt.rn.f16x2.f32 %0, %1, %2;" : "=r"(r) : "f"(hi), "f"(lo));
    return r;
}
__device__ __forceinline__ void mma_f16(float* c, const uint32_t* a, uint32_t b0, uint32_t b1) {
    asm volatile(
        "mma.sync.aligned.m16n8k16.row.col.f32.f16.f16.f32 "
        "{%0,%1,%2,%3}, {%4,%5,%6,%7}, {%8,%9}, {%0,%1,%2,%3};"
        : "+f"(c[0]), "+f"(c[1]), "+f"(c[2]), "+f"(c[3])
        : "r"(a[0]), "r"(a[1]), "r"(a[2]), "r"(a[3]), "r"(b0), "r"(b1));
}

// ---------------------------------------------------------------------------
// P0: pack W1 [D,U] -> g_w1p (fp16, m16n8k16 B-fragment order).  (R7-proven)
// ---------------------------------------------------------------------------
__global__ void pack_w1(const float* __restrict__ W1) {
    int idx = blockIdx.x * 256 + threadIdx.x;  // 0..262143
    int d = idx >> 9, u = idx & 511;
    __half v = __float2half_rn(W1[idx]);
    int kc6 = d >> 6, ks = (d >> 4) & 3, r = d & 15;
    int tg = (r & 7) >> 1, hidx = (r >> 3) * 2 + (r & 1);
    int nsub = u >> 7, un = u & 127;
    g_w1p[(size_t)(nsub * 8 + kc6) * 8192 + ((ks * 128 + un) * 4 + tg) * 4 + hidx] = v;
}

// ---------------------------------------------------------------------------
// P1: g_projh[b,u] = hidden[b,:] . W2[:,u] + b2[u] + b1[u]   (R7-proven)
// ---------------------------------------------------------------------------
__global__ void projh_kernel(const float* __restrict__ hidden,
                             const float* __restrict__ W2,
                             const float* __restrict__ b1,
                             const float* __restrict__ b2) {
    __shared__ float hs[DD];
    int b = blockIdx.x, u = threadIdx.x;  // 512 threads
    hs[u] = hidden[b * DD + u];
    __syncthreads();
    float acc = b1[u] + b2[u];
#pragma unroll 16
    for (int d = 0; d < DD; d++) acc = fmaf(hs[d], W2[d * UU + u], acc);
    g_projh[b * UU + u] = acc;
}

// ---------------------------------------------------------------------------
// K1: fused GEMM 128x512x512 + tanh + V-contract + tile softmax stats +
//     partial context from the fp16 A tile already resident in smem.
// smem: packA[8][16KB] | B[2][32KB] | projh | V(reused as ws/red) | logit
// ---------------------------------------------------------------------------
#define PACKA_OFF 0                    // 131072 B (8 chunks * 16KB)
#define B_OFF 131072
#define B_STAGE_B 32768
#define PROJ_OFF 196608
#define V_OFF 198656
#define LOG_OFF 200704
#define SMEM_BYTES 201216

__device__ __forceinline__ void load_b(uint32_t sb, int c, int tid) {
    uint32_t bbase = sb + B_OFF + (c & 1) * B_STAGE_B;
    const int nc = c >> 3, kc6 = c & 7;
#pragma unroll
    for (int sub = 0; sub < 2; sub++) {
        const __half* Bg = g_w1p + (size_t)((nc * 2 + sub) * 8 + kc6) * 8192;
#pragma unroll
        for (int j = 0; j < 4; j++) {
            int q = tid + j * 256;
            cp16s(bbase + sub * 16384 + q * 16, Bg + q * 8);
        }
    }
    CP_COMMIT();
}

__device__ __forceinline__ void convertA(char* smem, const float* __restrict__ features,
                                         int m0, int kc, int tid) {
    uint4* pk = (uint4*)(smem + PACKA_OFF) + kc * 1024;
#pragma unroll
    for (int j = 0; j < 4; j++) {
        int q = tid + j * 256;
        int ln = q & 31, rest = q >> 5;
        int mt8 = rest >> 2, ks = rest & 3;
        int gq = ln >> 2, tq = ln & 3;
        int mA = mt8 * 16 + gq;
        const float* fA = features + (size_t)(m0 + mA) * DD + kc * 64 + ks * 16 + 2 * tq;
        const float* fB = fA + 8 * DD;
        float2 xA0 = __ldg((const float2*)fA);
        float2 xB0 = __ldg((const float2*)fB);
        float2 xA1 = __ldg((const float2*)(fA + 8));
        float2 xB1 = __ldg((const float2*)(fB + 8));
        uint4 v;
        v.x = packh2(xA0.x, xA0.y);
        v.y = packh2(xB0.x, xB0.y);
        v.z = packh2(xA1.x, xA1.y);
        v.w = packh2(xB1.x, xB1.y);
        pk[q] = v;
    }
}

__global__ void __launch_bounds__(256, 1)
fused_score_kernel(const float* __restrict__ features,
                   const float* __restrict__ V,
                   const float* __restrict__ bv) {
    extern __shared__ __align__(128) char smem[];
    const uint32_t sb = smem_u32(smem);
    const int tid = threadIdx.x;
    const int warp = tid >> 5, lane = tid & 31;
    const int g = lane >> 2, tg = lane & 3;
    const int wm = warp >> 2, wn = warp & 3;
    const int m0 = blockIdx.x * 128;

    float* projh_s = (float*)(smem + PROJ_OFF);
    float* Vs = (float*)(smem + V_OFF);
    float* logit_s = (float*)(smem + LOG_OFF);
    const float bv0 = bv[0];

    load_b(sb, 0, tid);
    convertA(smem, features, m0, 0, tid);
    for (int i = tid; i < 512; i += 256) {
        projh_s[i] = g_projh[(m0 >> 11) * UU + i];
        Vs[i] = V[i];
    }
    if (tid < 128) logit_s[tid] = 0.f;

    const uint4* pkA = (const uint4*)(smem + PACKA_OFF);
    float c[4][8][4];

    for (int cc = 0; cc < 16; cc++) {
        const int s = cc & 1;
        const int kcA = cc & 7;
        if (kcA == 0 && (cc >> 3) == 0) {
#pragma unroll
            for (int i = 0; i < 4; i++)
#pragma unroll
                for (int j = 0; j < 8; j++)
#pragma unroll
                    for (int k = 0; k < 4; k++) c[i][j][k] = 0.f;
        }
        if (kcA == 0 && (cc >> 3) == 1) {
#pragma unroll
            for (int i = 0; i < 4; i++)
#pragma unroll
                for (int j = 0; j < 8; j++)
#pragma unroll
                    for (int k = 0; k < 4; k++) c[i][j][k] = 0.f;
        }

        asm volatile("cp.async.wait_group 0;" ::: "memory");
        __syncthreads();
        if (cc + 1 < 16) load_b(sb, cc + 1, tid);

        const char* Bs = smem + B_OFF + s * B_STAGE_B + (wn >> 1) * 16384;
        const int nloc0 = (wn & 1) * 64;
#pragma unroll
        for (int ks = 0; ks < 4; ks++) {
            uint32_t a[4][4];
#pragma unroll
            for (int mt = 0; mt < 4; mt++) {
                uint4 v = pkA[kcA * 1024 + ((wm * 4 + mt) * 4 + ks) * 32 + lane];
                a[mt][0] = v.x; a[mt][1] = v.y; a[mt][2] = v.z; a[mt][3] = v.w;
            }
            uint32_t b[8][2];
#pragma unroll
            for (int nt = 0; nt < 8; nt++) {
                int nl = nloc0 + nt * 8 + g;
                uint2 bp = *(const uint2*)(Bs + ((ks * 128 + nl) * 4 + tg) * 8);
                b[nt][0] = bp.x; b[nt][1] = bp.y;
            }
#pragma unroll
            for (int mt = 0; mt < 4; mt++)
#pragma unroll
                for (int nt = 0; nt < 8; nt++)
                    mma_f16(c[mt][nt], a[mt], b[nt][0], b[nt][1]);
        }

        if (cc + 1 < 8) convertA(smem, features, m0, cc + 1, tid);

        if (kcA == 7) {
            const int nc = cc >> 3;
#pragma unroll
            for (int mt = 0; mt < 4; mt++) {
                float p0 = 0.f, p1 = 0.f;
#pragma unroll
                for (int nt = 0; nt < 8; nt++) {
                    int u0 = nc * 256 + wn * 64 + nt * 8 + 2 * tg;
                    float ph0 = projh_s[u0], ph1 = projh_s[u0 + 1];
                    float v0 = Vs[u0], v1 = Vs[u0 + 1];
                    p0 += tanhap(c[mt][nt][0] + ph0) * v0;
                    p0 += tanhap(c[mt][nt][1] + ph1) * v1;
                    p1 += tanhap(c[mt][nt][2] + ph0) * v0;
                    p1 += tanhap(c[mt][nt][3] + ph1) * v1;
                }
                p0 += __shfl_xor_sync(0xffffffffu, p0, 1);
                p0 += __shfl_xor_sync(0xffffffffu, p0, 2);
                p1 += __shfl_xor_sync(0xffffffffu, p1, 1);
                p1 += __shfl_xor_sync(0xffffffffu, p1, 2);
                if (tg == 0) {
                    atomicAdd(&logit_s[wm * 64 + mt * 16 + g], p0);
                    atomicAdd(&logit_s[wm * 64 + mt * 16 + 8 + g], p1);
                }
            }
        }
    }
    __syncthreads();
    if (tid < 128) g_logits[m0 + tid] = logit_s[tid] + bv0;

    // ---- extended epilogue: tile softmax stats + partial context ----
    float* ws = Vs;                 // 128 weights (Vs dead now)
    float* red2 = Vs + 256;         // 8 floats
    if (tid < 128) {
        float l = logit_s[tid] + bv0;
        float mm = l;
#pragma unroll
        for (int off = 16; off; off >>= 1) mm = fmaxf(mm, __shfl_xor_sync(0xffffffffu, mm, off));
        if (lane == 0) red2[warp] = mm;
    }
    __syncthreads();
    float mtile = fmaxf(fmaxf(red2[0], red2[1]), fmaxf(red2[2], red2[3]));
    if (tid < 128) {
        float w = __expf(logit_s[tid] + bv0 - mtile);
        ws[tid] = w;
#pragma unroll
        for (int off = 16; off; off >>= 1) w += __shfl_xor_sync(0xffffffffu, w, off);
        if (lane == 0) red2[4 + warp] = w;
    }
    __syncthreads();
    if (tid == 0) {
        g_tm[blockIdx.x] = mtile;
        g_ts[blockIdx.x] = red2[4] + red2[5] + red2[6] + red2[7];
    }
    // pctx[d] = sum_t ws[t] * feat16[t][d], read from packA fragments
    {
        int d0 = tid * 2;
        int kc = d0 >> 6, rem = d0 & 63;
        int ks = rem >> 4, r2 = rem & 15;
        int pairB = (r2 >> 3) & 1, tq = (r2 & 7) >> 1;
        const char* base = smem + PACKA_OFF + kc * 16384 + ks * 512 + tq * 16 + pairB * 8;
        float a0 = 0.f, a1 = 0.f;
#pragma unroll
        for (int mt8 = 0; mt8 < 8; mt8++) {
#pragma unroll
            for (int gq = 0; gq < 8; gq++) {
                uint2 hv = *(const uint2*)(base + mt8 * 2048 + gq * 64);
                float2 lo = __half22float2(*(const __half2*)&hv.x);
                float2 hi = __half22float2(*(const __half2*)&hv.y);
                float w0 = ws[mt8 * 16 + gq], w1 = ws[mt8 * 16 + gq + 8];
                a0 = fmaf(w0, lo.x, fmaf(w1, hi.x, a0));
                a1 = fmaf(w0, lo.y, fmaf(w1, hi.y, a1));
            }
        }
        g_pctx[(size_t)blockIdx.x * 512 + d0] = a0;
        g_pctx[(size_t)blockIdx.x * 512 + d0 + 1] = a1;
    }
}

// ---------------------------------------------------------------------------
// K2: combine — exact softmax across the 16 tiles of each batch:
//     M = max m_i, S = sum e^{m_i-M} s_i; context and attn outputs.
// ---------------------------------------------------------------------------
__global__ void combine_kernel(float* __restrict__ out) {
    int b = blockIdx.x, tid = threadIdx.x;  // 512 threads
    __shared__ float fw[16];
    __shared__ float sM, sI;
    if (tid == 0) {
        float M = -3.4e38f;
        for (int i = 0; i < 16; i++) M = fmaxf(M, g_tm[b * 16 + i]);
        float S = 0.f;
        for (int i = 0; i < 16; i++) {
            float f = __expf(g_tm[b * 16 + i] - M);
            fw[i] = f;
            S += f * g_ts[b * 16 + i];
        }
        sM = M; sI = 1.0f / S;
    }
    __syncthreads();
    float M = sM, invS = sI;

    float acc = 0.f;
#pragma unroll
    for (int i = 0; i < 16; i++)
        acc = fmaf(fw[i], g_pctx[(size_t)(b * 16 + i) * 512 + tid], acc);
    out[b * DD + tid] = acc * invS;

#pragma unroll
    for (int k = 0; k < 4; k++) {
        int t = tid + k * 512;
        out[BB * DD + b * TT + t] = __expf(g_logits[b * TT + t] - M) * invS;
    }
}

// ---------------------------------------------------------------------------
extern "C" void kernel_launch(void* const* d_in, const int* in_sizes, int n_in,
                              void* d_out, int out_size) {
    const float* features = (const float*)d_in[0];
    const float* hidden   = (const float*)d_in[1];
    const float* W1       = (const float*)d_in[2];
    const float* b1       = (const float*)d_in[3];
    const float* W2       = (const float*)d_in[4];
    const float* b2       = (const float*)d_in[5];
    const float* V        = (const float*)d_in[6];
    const float* bv       = (const float*)d_in[7];
    float* out = (float*)d_out;

    cudaFuncSetAttribute(fused_score_kernel,
                         cudaFuncAttributeMaxDynamicSharedMemorySize, SMEM_BYTES);

    pack_w1<<<1024, 256>>>(W1);
    projh_kernel<<<BB, UU>>>(hidden, W2, b1, b2);
    fused_score_kernel<<<NT, 256, SMEM_BYTES>>>(features, V, bv);
    combine_kernel<<<BB, 512>>>(out);
}

// round 17
// speedup vs baseline: 1.4142x; 1.1330x over previous
#include <cuda_runtime.h>
#include <cuda_fp16.h>
#include <cstdint>

#define BB 32
#define TT 2048
#define DD 512
#define UU 512
#define NT 512                 // tiles of 128 rows

// Scratch (no device allocation allowed)
__device__ float g_projh[BB * UU];       // hidden@W2 + b2 + b1 (b1 folded)
__device__ float g_logits[BB * TT];
__device__ float g_tm[NT];               // per-tile logit max
__device__ float g_ts[NT];               // per-tile sum exp(l - m)
__device__ float g_pctx[NT * DD];        // per-tile partial context
__device__ __half g_w1p[UU * DD];        // W1 fp16, fragment-packed

// ---------------------------------------------------------------------------
// helpers
// ---------------------------------------------------------------------------
__device__ __forceinline__ uint32_t smem_u32(const void* p) {
    uint32_t a;
    asm("{ .reg .u64 t; cvta.to.shared.u64 t, %1; cvt.u32.u64 %0, t; }" : "=r"(a) : "l"(p));
    return a;
}
__device__ __forceinline__ float tanhap(float x) {
    float y;
    asm("tanh.approx.f32 %0, %1;" : "=f"(y) : "f"(x));
    return y;
}
__device__ __forceinline__ void cp16s(uint32_t s, const void* g) {
    asm volatile("cp.async.cg.shared.global [%0], [%1], 16;" :: "r"(s), "l"(g) : "memory");
}
#define CP_COMMIT() asm volatile("cp.async.commit_group;" ::: "memory")

__device__ __forceinline__ uint32_t packh2(float lo, float hi) {
    uint32_t r;
    asm("cvt.rn.f16x2.f32 %0, %1, %2;" : "=r"(r) : "f"(hi), "f"(lo));
    return r;
}
__device__ __forceinline__ void mma_f16(float* c, const uint32_t* a, uint32_t b0, uint32_t b1) {
    asm volatile(
        "mma.sync.aligned.m16n8k16.row.col.f32.f16.f16.f32 "
        "{%0,%1,%2,%3}, {%4,%5,%6,%7}, {%8,%9}, {%0,%1,%2,%3};"
        : "+f"(c[0]), "+f"(c[1]), "+f"(c[2]), "+f"(c[3])
        : "r"(a[0]), "r"(a[1]), "r"(a[2]), "r"(a[3]), "r"(b0), "r"(b1));
}

// ---------------------------------------------------------------------------
// P0: pack W1 [D,U] -> g_w1p (fp16, m16n8k16 B-fragment order).  (R7-proven)
// ---------------------------------------------------------------------------
__global__ void pack_w1(const float* __restrict__ W1) {
    int idx = blockIdx.x * 256 + threadIdx.x;  // 0..262143
    int d = idx >> 9, u = idx & 511;
    __half v = __float2half_rn(W1[idx]);
    int kc6 = d >> 6, ks = (d >> 4) & 3, r = d & 15;
    int tg = (r & 7) >> 1, hidx = (r >> 3) * 2 + (r & 1);
    int nsub = u >> 7, un = u & 127;
    g_w1p[(size_t)(nsub * 8 + kc6) * 8192 + ((ks * 128 + un) * 4 + tg) * 4 + hidx] = v;
}

// ---------------------------------------------------------------------------
// P1: g_projh[b,u] = hidden[b,:].W2[:,u] + b2[u] + b1[u]
// grid (8 uchunks, 32 b), 256 thr: 64 u x 4 k-segments, smem reduce.
// ---------------------------------------------------------------------------
__global__ void projh_kernel(const float* __restrict__ hidden,
                             const float* __restrict__ W2,
                             const float* __restrict__ b1,
                             const float* __restrict__ b2) {
    __shared__ float hs[DD];
    __shared__ float part[3][64];
    int b = blockIdx.y, uq = blockIdx.x;
    int tid = threadIdx.x;
    hs[tid] = hidden[b * DD + tid];
    hs[tid + 256] = hidden[b * DD + tid + 256];
    __syncthreads();
    int tu = tid & 63, kseg = tid >> 6;
    int u = uq * 64 + tu;
    float acc = 0.f;
    const float* w = W2 + (size_t)(kseg * 128) * UU + u;
    const float* h = hs + kseg * 128;
#pragma unroll 16
    for (int d = 0; d < 128; d++) acc = fmaf(h[d], w[(size_t)d * UU], acc);
    if (kseg) part[kseg - 1][tu] = acc;
    __syncthreads();
    if (kseg == 0)
        g_projh[b * UU + u] = acc + part[0][tu] + part[1][tu] + part[2][tu] + b1[u] + b2[u];
}

// ---------------------------------------------------------------------------
// K1: fused GEMM 128x512x512 + tanh + V-contract + tile softmax stats +
//     partial context from the fp16 A tile resident in smem.
// A-convert split load/store around MMA halves to hide LDG latency.
// smem: packA[8][16KB] | B[2][32KB] | projh | V(reused) | logit
// ---------------------------------------------------------------------------
#define PACKA_OFF 0                    // 131072 B (8 chunks * 16KB)
#define B_OFF 131072
#define B_STAGE_B 32768
#define PROJ_OFF 196608
#define V_OFF 198656
#define LOG_OFF 200704
#define SMEM_BYTES 201216

__device__ __forceinline__ void load_b(uint32_t sb, int c, int tid) {
    uint32_t bbase = sb + B_OFF + (c & 1) * B_STAGE_B;
    const int nc = c >> 3, kc6 = c & 7;
#pragma unroll
    for (int sub = 0; sub < 2; sub++) {
        const __half* Bg = g_w1p + (size_t)((nc * 2 + sub) * 8 + kc6) * 8192;
#pragma unroll
        for (int j = 0; j < 4; j++) {
            int q = tid + j * 256;
            cp16s(bbase + sub * 16384 + q * 16, Bg + q * 8);
        }
    }
    CP_COMMIT();
}

// half = 0 -> j 0,1 ; half = 1 -> j 2,3
__device__ __forceinline__ void convA_load2(float2* v, const float* __restrict__ features,
                                            int m0, int kc, int half, int tid) {
#pragma unroll
    for (int jj = 0; jj < 2; jj++) {
        int j = half * 2 + jj;
        int q = tid + j * 256;
        int ln = q & 31, rest = q >> 5;
        int mt8 = rest >> 2, ks = rest & 3;
        int gq = ln >> 2, tq = ln & 3;
        int mA = mt8 * 16 + gq;
        const float* fA = features + (size_t)(m0 + mA) * DD + kc * 64 + ks * 16 + 2 * tq;
        const float* fB = fA + 8 * DD;
        v[jj * 4 + 0] = __ldg((const float2*)fA);
        v[jj * 4 + 1] = __ldg((const float2*)fB);
        v[jj * 4 + 2] = __ldg((const float2*)(fA + 8));
        v[jj * 4 + 3] = __ldg((const float2*)(fB + 8));
    }
}
__device__ __forceinline__ void convA_store2(char* smem, const float2* v,
                                             int kc, int half, int tid) {
    uint4* pk = (uint4*)(smem + PACKA_OFF) + kc * 1024;
#pragma unroll
    for (int jj = 0; jj < 2; jj++) {
        int j = half * 2 + jj;
        int q = tid + j * 256;
        uint4 o;
        o.x = packh2(v[jj * 4 + 0].x, v[jj * 4 + 0].y);
        o.y = packh2(v[jj * 4 + 1].x, v[jj * 4 + 1].y);
        o.z = packh2(v[jj * 4 + 2].x, v[jj * 4 + 2].y);
        o.w = packh2(v[jj * 4 + 3].x, v[jj * 4 + 3].y);
        pk[q] = o;
    }
}
// full convert (prologue, chunk 0 only)
__device__ __forceinline__ void convertA(char* smem, const float* __restrict__ features,
                                         int m0, int kc, int tid) {
    float2 v[8];
    convA_load2(v, features, m0, kc, 0, tid);
    convA_store2(smem, v, kc, 0, tid);
    convA_load2(v, features, m0, kc, 1, tid);
    convA_store2(smem, v, kc, 1, tid);
}

__global__ void __launch_bounds__(256, 1)
fused_score_kernel(const float* __restrict__ features,
                   const float* __restrict__ V,
                   const float* __restrict__ bv) {
    extern __shared__ __align__(128) char smem[];
    const uint32_t sb = smem_u32(smem);
    const int tid = threadIdx.x;
    const int warp = tid >> 5, lane = tid & 31;
    const int g = lane >> 2, tg = lane & 3;
    const int wm = warp >> 2, wn = warp & 3;
    const int m0 = blockIdx.x * 128;

    float* projh_s = (float*)(smem + PROJ_OFF);
    float* Vs = (float*)(smem + V_OFF);
    float* logit_s = (float*)(smem + LOG_OFF);
    const float bv0 = bv[0];

    load_b(sb, 0, tid);
    convertA(smem, features, m0, 0, tid);
    for (int i = tid; i < 512; i += 256) {
        projh_s[i] = g_projh[(m0 >> 11) * UU + i];
        Vs[i] = V[i];
    }
    if (tid < 128) logit_s[tid] = 0.f;

    const uint4* pkA = (const uint4*)(smem + PACKA_OFF);
    float c[4][8][4];

    for (int cc = 0; cc < 16; cc++) {
        const int s = cc & 1;
        const int kcA = cc & 7;
        if (kcA == 0) {
#pragma unroll
            for (int i = 0; i < 4; i++)
#pragma unroll
                for (int j = 0; j < 8; j++)
#pragma unroll
                    for (int k = 0; k < 4; k++) c[i][j][k] = 0.f;
        }

        asm volatile("cp.async.wait_group 0;" ::: "memory");
        __syncthreads();
        if (cc + 1 < 16) load_b(sb, cc + 1, tid);

        const char* Bs = smem + B_OFF + s * B_STAGE_B + (wn >> 1) * 16384;
        const int nloc0 = (wn & 1) * 64;
        const bool doConv = (cc + 1 < 8);
        const int cnext = cc + 1;
        float2 v[8];
        if (doConv) convA_load2(v, features, m0, cnext, 0, tid);

#pragma unroll
        for (int ks = 0; ks < 4; ks++) {
            uint32_t a[4][4];
#pragma unroll
            for (int mt = 0; mt < 4; mt++) {
                uint4 av = pkA[kcA * 1024 + ((wm * 4 + mt) * 4 + ks) * 32 + lane];
                a[mt][0] = av.x; a[mt][1] = av.y; a[mt][2] = av.z; a[mt][3] = av.w;
            }
            uint32_t b[8][2];
#pragma unroll
            for (int nt = 0; nt < 8; nt++) {
                int nl = nloc0 + nt * 8 + g;
                uint2 bp = *(const uint2*)(Bs + ((ks * 128 + nl) * 4 + tg) * 8);
                b[nt][0] = bp.x; b[nt][1] = bp.y;
            }
#pragma unroll
            for (int mt = 0; mt < 4; mt++)
#pragma unroll
                for (int nt = 0; nt < 8; nt++)
                    mma_f16(c[mt][nt], a[mt], b[nt][0], b[nt][1]);

            if (ks == 1 && doConv) {
                convA_store2(smem, v, cnext, 0, tid);
                convA_load2(v, features, m0, cnext, 1, tid);
            }
        }
        if (doConv) convA_store2(smem, v, cnext, 1, tid);

        if (kcA == 7) {
            const int nc = cc >> 3;
#pragma unroll
            for (int mt = 0; mt < 4; mt++) {
                float p0 = 0.f, p1 = 0.f;
#pragma unroll
                for (int nt = 0; nt < 8; nt++) {
                    int u0 = nc * 256 + wn * 64 + nt * 8 + 2 * tg;
                    float ph0 = projh_s[u0], ph1 = projh_s[u0 + 1];
                    float v0 = Vs[u0], v1 = Vs[u0 + 1];
                    p0 += tanhap(c[mt][nt][0] + ph0) * v0;
                    p0 += tanhap(c[mt][nt][1] + ph1) * v1;
                    p1 += tanhap(c[mt][nt][2] + ph0) * v0;
                    p1 += tanhap(c[mt][nt][3] + ph1) * v1;
                }
                p0 += __shfl_xor_sync(0xffffffffu, p0, 1);
                p0 += __shfl_xor_sync(0xffffffffu, p0, 2);
                p1 += __shfl_xor_sync(0xffffffffu, p1, 1);
                p1 += __shfl_xor_sync(0xffffffffu, p1, 2);
                if (tg == 0) {
                    atomicAdd(&logit_s[wm * 64 + mt * 16 + g], p0);
                    atomicAdd(&logit_s[wm * 64 + mt * 16 + 8 + g], p1);
                }
            }
        }
    }
    __syncthreads();
    if (tid < 128) g_logits[m0 + tid] = logit_s[tid] + bv0;

    // ---- extended epilogue: tile softmax stats + partial context ----
    float* ws = Vs;
    float* red2 = Vs + 256;
    if (tid < 128) {
        float l = logit_s[tid] + bv0;
        float mm = l;
#pragma unroll
        for (int off = 16; off; off >>= 1) mm = fmaxf(mm, __shfl_xor_sync(0xffffffffu, mm, off));
        if (lane == 0) red2[warp] = mm;
    }
    __syncthreads();
    float mtile = fmaxf(fmaxf(red2[0], red2[1]), fmaxf(red2[2], red2[3]));
    if (tid < 128) {
        float w = __expf(logit_s[tid] + bv0 - mtile);
        ws[tid] = w;
#pragma unroll
        for (int off = 16; off; off >>= 1) w += __shfl_xor_sync(0xffffffffu, w, off);
        if (lane == 0) red2[4 + warp] = w;
    }
    __syncthreads();
    if (tid == 0) {
        g_tm[blockIdx.x] = mtile;
        g_ts[blockIdx.x] = red2[4] + red2[5] + red2[6] + red2[7];
    }
    {
        int d0 = tid * 2;
        int kc = d0 >> 6, rem = d0 & 63;
        int ks = rem >> 4, r2 = rem & 15;
        int pairB = (r2 >> 3) & 1, tq = (r2 & 7) >> 1;
        const char* base = smem + PACKA_OFF + kc * 16384 + ks * 512 + tq * 16 + pairB * 8;
        float a0 = 0.f, a1 = 0.f;
#pragma unroll
        for (int mt8 = 0; mt8 < 8; mt8++) {
#pragma unroll
            for (int gq = 0; gq < 8; gq++) {
                uint2 hv = *(const uint2*)(base + mt8 * 2048 + gq * 64);
                float2 lo = __half22float2(*(const __half2*)&hv.x);
                float2 hi = __half22float2(*(const __half2*)&hv.y);
                float w0 = ws[mt8 * 16 + gq], w1 = ws[mt8 * 16 + gq + 8];
                a0 = fmaf(w0, lo.x, fmaf(w1, hi.x, a0));
                a1 = fmaf(w0, lo.y, fmaf(w1, hi.y, a1));
            }
        }
        g_pctx[(size_t)blockIdx.x * 512 + d0] = a0;
        g_pctx[(size_t)blockIdx.x * 512 + d0 + 1] = a1;
    }
}

// ---------------------------------------------------------------------------
// K2: combine — grid (5, BB): q=0 context, q=1..4 attn quarters.
// ---------------------------------------------------------------------------
__global__ void combine_kernel(float* __restrict__ out) {
    int b = blockIdx.y, q = blockIdx.x, tid = threadIdx.x;  // 512 threads
    __shared__ float fw[16];
    __shared__ float sM, sI;
    if (tid == 0) {
        float M = -3.4e38f;
        for (int i = 0; i < 16; i++) M = fmaxf(M, g_tm[b * 16 + i]);
        float S = 0.f;
        for (int i = 0; i < 16; i++) {
            float f = __expf(g_tm[b * 16 + i] - M);
            fw[i] = f;
            S += f * g_ts[b * 16 + i];
        }
        sM = M; sI = 1.0f / S;
    }
    __syncthreads();

    if (q == 0) {
        float acc = 0.f;
#pragma unroll
        for (int i = 0; i < 16; i++)
            acc = fmaf(fw[i], g_pctx[(size_t)(b * 16 + i) * 512 + tid], acc);
        out[b * DD + tid] = acc * sI;
    } else {
        int t = (q - 1) * 512 + tid;
        out[BB * DD + b * TT + t] = __expf(g_logits[b * TT + t] - sM) * sI;
    }
}

// ---------------------------------------------------------------------------
extern "C" void kernel_launch(void* const* d_in, const int* in_sizes, int n_in,
                              void* d_out, int out_size) {
    const float* features = (const float*)d_in[0];
    const float* hidden   = (const float*)d_in[1];
    const float* W1       = (const float*)d_in[2];
    const float* b1       = (const float*)d_in[3];
    const float* W2       = (const float*)d_in[4];
    const float* b2       = (const float*)d_in[5];
    const float* V        = (const float*)d_in[6];
    const float* bv       = (const float*)d_in[7];
    float* out = (float*)d_out;

    cudaFuncSetAttribute(fused_score_kernel,
                         cudaFuncAttributeMaxDynamicSharedMemorySize, SMEM_BYTES);

    pack_w1<<<1024, 256>>>(W1);
    projh_kernel<<<dim3(8, BB), 256>>>(hidden, W2, b1, b2);
    fused_score_kernel<<<NT, 256, SMEM_BYTES>>>(features, V, bv);
    combine_kernel<<<dim3(5, BB), 512>>>(out);
}